// round 17
// baseline (speedup 1.0000x reference)
#include <cuda.h>
#include <cuda_runtime.h>
#include <math.h>
#include <stdint.h>

#define NEL 32
#define NUP 16
#define NI  32
#define NL  16
#define NK  16
#define H1  128
#define H2  4
#define FLEN 392
#define GRID 64
#define THREADS 512

#define ROWS_PER_STAGE 98
#define STAGE_BYTES (ROWS_PER_STAGE * 64 * 4)   // 25088
#define NSTAGE 4
#define DYN_BYTES (NSTAGE * STAGE_BYTES)        // 100352

// ---- device-global state (no allocation allowed) ----
__device__ float g_sh[2][NEL][H1];
__device__ float g_rN[NEL][NI];
__device__ float g_phi[NK][2][16][16];
__device__ float g_det[NK][2];
__device__ unsigned g_bar[NL + 2];

// ---------------- R2's barrier, verbatim ----------------
__device__ __forceinline__ unsigned ld_acq(const unsigned* p) {
    unsigned v;
    asm volatile("ld.acquire.gpu.global.u32 %0, [%1];" : "=r"(v) : "l"(p) : "memory");
    return v;
}
__device__ __forceinline__ void red_rel_add1(unsigned* p) {
    asm volatile("red.release.gpu.global.add.u32 [%0], 1;" :: "l"(p) : "memory");
}
__device__ __forceinline__ void bar_arrive(int idx) {
    __syncthreads();
    if (threadIdx.x == 0) red_rel_add1(&g_bar[idx]);
}
__device__ __forceinline__ void bar_wait(int idx, unsigned target) {
    if (threadIdx.x == 0) {
        while (ld_acq(&g_bar[idx]) < target) { }
    }
    __syncthreads();
}

// ---------------- TMA / mbarrier helpers ----------------
__device__ __forceinline__ void mbar_init(uint32_t mbar, unsigned cnt) {
    asm volatile("mbarrier.init.shared.b64 [%0], %1;" :: "r"(mbar), "r"(cnt) : "memory");
}
__device__ __forceinline__ void mbar_expect_tx(uint32_t mbar, unsigned bytes) {
    asm volatile("mbarrier.arrive.expect_tx.shared.b64 _, [%0], %1;"
                 :: "r"(mbar), "r"(bytes) : "memory");
}
__device__ __forceinline__ void mbar_wait(uint32_t mbar, unsigned parity) {
    asm volatile(
        "{\n\t"
        ".reg .pred P;\n\t"
        "WL_%=:\n\t"
        "mbarrier.try_wait.parity.acquire.cta.shared::cta.b64 P, [%0], %1, 0x989680;\n\t"
        "@P bra WD_%=;\n\t"
        "bra WL_%=;\n\t"
        "WD_%=:\n\t"
        "}"
        :: "r"(mbar), "r"(parity) : "memory");
}
__device__ __forceinline__ void tma_load_3d(uint32_t dst, const CUtensorMap* tm,
                                            int c0, int c1, int c2, uint32_t mbar) {
    asm volatile(
        "cp.async.bulk.tensor.3d.shared::cta.global.tile.mbarrier::complete_tx::bytes "
        "[%0], [%1, {%2, %3, %4}], [%5];"
        :: "r"(dst), "l"(tm), "r"(c0), "r"(c1), "r"(c2), "r"(mbar) : "memory");
}

// ---------------------------------------------------------------------------
// Preprocess: sh^0 + rN + zero counters (every replay)
// ---------------------------------------------------------------------------
__global__ void pre_kernel(const float* __restrict__ ep,
                           const float* __restrict__ nuc) {
    int t = threadIdx.x;
    if (t < NL + 2) g_bar[t] = 0;
    for (int p = t; p < NEL * NI; p += blockDim.x) {
        int j = p >> 5, m = p & 31;
        float dx = ep[j * 3 + 0] - nuc[m * 3 + 0];
        float dy = ep[j * 3 + 1] - nuc[m * 3 + 1];
        float dz = ep[j * 3 + 2] - nuc[m * 3 + 2];
        float r  = sqrtf(dx * dx + dy * dy + dz * dz);
        g_sh[0][j][m * 3 + 0] = dx;
        g_sh[0][j][m * 3 + 1] = dy;
        g_sh[0][j][m * 3 + 2] = dz;
        g_sh[0][j][3 * NI + m] = r;
        g_rN[j][m] = r;
    }
}

// ---------------------------------------------------------------------------
// Fused persistent kernel. 64 blocks x 512 threads.
//   block b: electron n = b>>1, output half = b&1 (64 cols).
//   warp 15 owns the full dh chain for electron n (lane = pair j).
//   Weights stream via TMA in 4 quarter-layer stages.
// ---------------------------------------------------------------------------
__global__ void __launch_bounds__(THREADS, 1) fused_kernel(
    const __grid_constant__ CUtensorMap tmap,
    const float* __restrict__ ep, const float* __restrict__ nuc,
    const float* __restrict__ b,  const float* __restrict__ w,
    const float* __restrict__ c,  const float* __restrict__ fw,
    const float* __restrict__ fb, const float* __restrict__ pi,
    const float* __restrict__ sigma, const float* __restrict__ omega,
    float* __restrict__ out)
{
    extern __shared__ __align__(128) char dyn[];
    __shared__ __align__(8) unsigned long long mbar_st[NSTAGE];
    __shared__ float fsh[FLEN];          // [own sh 128 | g_up 128 | g_dn 128 | dg 8]
    __shared__ float part_s[16][65];
    __shared__ float dg_s[8];
    __shared__ float A[16][17];
    __shared__ float fac[16];
    __shared__ int   pivs;
    __shared__ float dsh;

    const int t     = threadIdx.x;
    const int n     = blockIdx.x >> 1;
    const int half  = blockIdx.x & 1;
    const int obase = half * 64;
    const int q     = t & 15;           // output quad (4 cols)
    const int s     = t >> 4;           // row slice 0..31
    const int lane  = t & 31, wrp = t >> 5;

    const uint32_t dyn_s = (uint32_t)__cvta_generic_to_shared(dyn);
    uint32_t mb[NSTAGE];
#pragma unroll
    for (int i = 0; i < NSTAGE; i++)
        mb[i] = (uint32_t)__cvta_generic_to_shared(&mbar_st[i]);

    // ---- init mbarriers + layer-0 stages ----
    if (t == 0) {
#pragma unroll
        for (int i = 0; i < NSTAGE; i++) mbar_init(mb[i], 1);
    }
    __syncthreads();
    if (t == 0) {
#pragma unroll
        for (int st = 0; st < NSTAGE; st++) {
            mbar_expect_tx(mb[st], STAGE_BYTES);
            tma_load_3d(dyn_s + st * STAGE_BYTES, &tmap,
                        obase, st * ROWS_PER_STAGE, 0 * NEL + n, mb[st]);
        }
    }

    // ---- prologue: dh^0 in warp 15, dg for layer 0 ----
    float4 d4;
    if (wrp == 15) {
        int j = lane;
        float dx = ep[n * 3 + 0] - ep[j * 3 + 0];
        float dy = ep[n * 3 + 1] - ep[j * 3 + 1];
        float dz = ep[n * 3 + 2] - ep[j * 3 + 2];
        d4 = make_float4(dx, dy, dz, sqrtf(dx * dx + dy * dy + dz * dz));
        float4 sv = d4;
#pragma unroll
        for (int off = 8; off; off >>= 1) {
            sv.x += __shfl_down_sync(0xffffffffu, sv.x, off, 16);
            sv.y += __shfl_down_sync(0xffffffffu, sv.y, off, 16);
            sv.z += __shfl_down_sync(0xffffffffu, sv.z, off, 16);
            sv.w += __shfl_down_sync(0xffffffffu, sv.w, off, 16);
        }
        if (lane == 0) {
            dg_s[0] = sv.x * (1.f/16); dg_s[1] = sv.y * (1.f/16);
            dg_s[2] = sv.z * (1.f/16); dg_s[3] = sv.w * (1.f/16);
        }
        if (lane == 16) {
            dg_s[4] = sv.x * (1.f/16); dg_s[5] = sv.y * (1.f/16);
            dg_s[6] = sv.z * (1.f/16); dg_s[7] = sv.w * (1.f/16);
        }
    }
    __syncthreads();

#pragma unroll 1
    for (int l = 0; l < NL; l++) {
        const int cur = l & 1, nxt = cur ^ 1;
        const unsigned par = (unsigned)(l & 1);

        // ---- prefetch small operands ----
        float bias_r = 0.f;
        if (t < 64) bias_r = b[((size_t)l * NEL + n) * H1 + obase + t];
        float4 dw0, dw1, dw2, dw3, dc4;
        const bool do_d = (wrp == 15) && (l < NL - 1);
        if (do_d) {
            const float* wp = w + ((size_t)(l * NEL + n) * NEL + lane) * 16;
            dw0 = *reinterpret_cast<const float4*>(wp);
            dw1 = *reinterpret_cast<const float4*>(wp + 4);
            dw2 = *reinterpret_cast<const float4*>(wp + 8);
            dw3 = *reinterpret_cast<const float4*>(wp + 12);
            dc4 = *reinterpret_cast<const float4*>(
                c + ((size_t)(l * NEL + n) * NEL + lane) * 4);
        }

        // ---- chip barrier: previous layer visible ----
        if (l > 0) bar_wait(l - 1, GRID);

        // ---- build feature vector ----
        if (t < 128) {
            fsh[t] = __ldcg(&g_sh[cur][n][t]);
        } else if (t < 256) {
            int o = t - 128;
            float sv = 0.f;
#pragma unroll
            for (int r = 0; r < NUP; r++) sv += __ldcg(&g_sh[cur][r][o]);
            fsh[128 + o] = sv * (1.0f / 16);
        } else if (t < 384) {
            int o = t - 256;
            float sv = 0.f;
#pragma unroll
            for (int r = NUP; r < NEL; r++) sv += __ldcg(&g_sh[cur][r][o]);
            fsh[256 + o] = sv * (1.0f / 16);
        } else if (t < 392) {
            fsh[t] = dg_s[t - 384];
        }
        __syncthreads();

        // ---- matvec over 4 TMA stages ----
        float4 acc = make_float4(0.f, 0.f, 0.f, 0.f);
#pragma unroll
        for (int st = 0; st < NSTAGE; st++) {
            mbar_wait(mb[st], par);
            const float4* wst = (const float4*)(dyn + st * STAGE_BYTES);
            const int base = st * ROWS_PER_STAGE;
#pragma unroll
            for (int i = 0; i < 4; i++) {
                int r = s + 32 * i;
                if (r < ROWS_PER_STAGE) {
                    float sv = fsh[base + r];
                    float4 wv = wst[r * 16 + q];
                    acc.x += sv * wv.x; acc.y += sv * wv.y;
                    acc.z += sv * wv.z; acc.w += sv * wv.w;
                }
            }
        }

        // ---- dh update (warp 15, overlaps reduce) ----
        float4 od;
        if (do_d) {
            float o0 = d4.x * dw0.x + d4.y * dw1.x + d4.z * dw2.x + d4.w * dw3.x;
            float o1 = d4.x * dw0.y + d4.y * dw1.y + d4.z * dw2.y + d4.w * dw3.y;
            float o2 = d4.x * dw0.z + d4.y * dw1.z + d4.z * dw2.z + d4.w * dw3.z;
            float o3 = d4.x * dw0.w + d4.y * dw1.w + d4.z * dw2.w + d4.w * dw3.w;
            od.x = tanhf(o0 + dc4.x) + d4.x;
            od.y = tanhf(o1 + dc4.y) + d4.y;
            od.z = tanhf(o2 + dc4.z) + d4.z;
            od.w = tanhf(o3 + dc4.w) + d4.w;
        }

        // ---- reduce: fold the warp's two slices, then smem ----
        acc.x += __shfl_down_sync(0xffffffffu, acc.x, 16);
        acc.y += __shfl_down_sync(0xffffffffu, acc.y, 16);
        acc.z += __shfl_down_sync(0xffffffffu, acc.z, 16);
        acc.w += __shfl_down_sync(0xffffffffu, acc.w, 16);
        if (lane < 16) {
            part_s[wrp][lane * 4 + 0] = acc.x;
            part_s[wrp][lane * 4 + 1] = acc.y;
            part_s[wrp][lane * 4 + 2] = acc.z;
            part_s[wrp][lane * 4 + 3] = acc.w;
        }
        __syncthreads();

        // ---- refill stages for next layer (weights fully consumed) ----
        if (l + 1 < NL && t == 0) {
#pragma unroll
            for (int st = 0; st < NSTAGE; st++) {
                mbar_expect_tx(mb[st], STAGE_BYTES);
                tma_load_3d(dyn_s + st * STAGE_BYTES, &tmap,
                            obase, st * ROWS_PER_STAGE, (l + 1) * NEL + n, mb[st]);
            }
        }

        // ---- tail: 64 threads, one output column each ----
        if (t < 64) {
            float a = part_s[0][t];
#pragma unroll
            for (int ww = 1; ww < 16; ww++) a += part_s[ww][t];
            int o = obase + t;
            float val = tanhf(a + bias_r) + fsh[o];
            __stcg(&g_sh[nxt][n][o], val);
        }

        // ---- dh commit + dg for next layer ----
        if (do_d) {
            d4 = od;
            float4 sv = d4;
#pragma unroll
            for (int off = 8; off; off >>= 1) {
                sv.x += __shfl_down_sync(0xffffffffu, sv.x, off, 16);
                sv.y += __shfl_down_sync(0xffffffffu, sv.y, off, 16);
                sv.z += __shfl_down_sync(0xffffffffu, sv.z, off, 16);
                sv.w += __shfl_down_sync(0xffffffffu, sv.w, off, 16);
            }
            if (lane == 0) {
                dg_s[0] = sv.x * (1.f/16); dg_s[1] = sv.y * (1.f/16);
                dg_s[2] = sv.z * (1.f/16); dg_s[3] = sv.w * (1.f/16);
            }
            if (lane == 16) {
                dg_s[4] = sv.x * (1.f/16); dg_s[5] = sv.y * (1.f/16);
                dg_s[6] = sv.z * (1.f/16); dg_s[7] = sv.w * (1.f/16);
            }
        }
        bar_arrive(l);
    }

    // ================= phi (diagonal 16x16 blocks only) =================
    bar_wait(NL - 1, GRID);
    {
        // entry e = blockIdx.x*128 + (t>>2); 4-way split s4 = t&3
        const int e    = blockIdx.x * 128 + (t >> 2);
        const int s4   = t & 3;
        const int k    = e >> 9;
        const int rem  = e & 511;
        const int spin = rem >> 8;
        const int il   = (rem >> 4) & 15;
        const int jl   = rem & 15;
        const int i    = spin * 16 + il;
        const int j    = spin * 16 + jl;
        const float* fwp = fw + (size_t)(k * NEL + i) * H1;
        float dot = 0.f;
#pragma unroll
        for (int qq = 0; qq < 32; qq++)
            dot += fwp[s4 + 4 * qq] * __ldcg(&g_sh[0][j][s4 + 4 * qq]);
        const float* pip = pi    + (size_t)(k * NEL + i) * NI;
        const float* sgp = sigma + (size_t)(k * NEL + i) * NI;
        float env = 0.f;
#pragma unroll
        for (int qq = 0; qq < 8; qq++) {
            int m = s4 * 8 + qq;
            env += pip[m] * __expf(-fabsf(sgp[m]) * g_rN[j][m]);
        }
        dot += __shfl_down_sync(0xffffffffu, dot, 2, 4);
        dot += __shfl_down_sync(0xffffffffu, dot, 1, 4);
        env += __shfl_down_sync(0xffffffffu, env, 2, 4);
        env += __shfl_down_sync(0xffffffffu, env, 1, 4);
        if (s4 == 0)
            __stcg(&g_phi[k][spin][il][jl], (dot + fb[k * NEL + i]) * env);
    }
    bar_arrive(NL);

    // ================= determinants (blocks 0..31, one each) =================
    if (blockIdx.x < 32) {
        bar_wait(NL, GRID);
        const int k = blockIdx.x >> 1, spin = blockIdx.x & 1;
        const int r = (t >> 4) & 15, cc = t & 15;
        if (t < 256) A[r][cc] = __ldcg(&g_phi[k][spin][r][cc]);
        if (t == 0) dsh = 1.0f;
        __syncthreads();
        for (int pp = 0; pp < 16; pp++) {
            if (t == 0) {
                int best = pp;
                float bv = fabsf(A[pp][pp]);
                for (int rr = pp + 1; rr < 16; rr++) {
                    float v2 = fabsf(A[rr][pp]);
                    if (v2 > bv) { bv = v2; best = rr; }
                }
                pivs = best;
                if (best != pp) dsh = -dsh;
            }
            __syncthreads();
            int piv = pivs;
            if (piv != pp && t < 16) {
                float tmp = A[pp][t]; A[pp][t] = A[piv][t]; A[piv][t] = tmp;
            }
            __syncthreads();
            if (t < 16 && t > pp) fac[t] = A[t][pp] / A[pp][pp];
            if (t == 0) dsh *= A[pp][pp];
            __syncthreads();
            if (t < 256 && r > pp && cc > pp) A[r][cc] -= fac[r] * A[pp][cc];
            __syncthreads();
        }
        if (t == 0) __stcg(&g_det[k][spin], dsh);
        bar_arrive(NL + 1);
    }

    // ================= final reduction (block 0) =================
    if (blockIdx.x == 0) {
        bar_wait(NL + 1, 32);
        if (t < 32) {
            float vv = (t < NK) ? omega[t] * __ldcg(&g_det[t][0]) * __ldcg(&g_det[t][1])
                                : 0.0f;
#pragma unroll
            for (int off = 16; off; off >>= 1)
                vv += __shfl_down_sync(0xffffffffu, vv, off);
            if (t == 0) out[0] = vv;
        }
    }
}

// ---------------------------------------------------------------------------
// Host side
// ---------------------------------------------------------------------------
typedef CUresult (*PFN_tme)(CUtensorMap*, CUtensorMapDataType, cuuint32_t, void*,
                            const cuuint64_t*, const cuuint64_t*, const cuuint32_t*,
                            const cuuint32_t*, CUtensorMapInterleave, CUtensorMapSwizzle,
                            CUtensorMapL2promotion, CUtensorMapFloatOOBfill);

extern "C" void kernel_launch(void* const* d_in, const int* in_sizes, int n_in,
                              void* d_out, int out_size) {
    const float* ep    = (const float*)d_in[0];
    const float* nuc   = (const float*)d_in[1];
    const float* v     = (const float*)d_in[2];
    const float* b     = (const float*)d_in[3];
    const float* w     = (const float*)d_in[4];
    const float* c     = (const float*)d_in[5];
    const float* fw    = (const float*)d_in[6];
    const float* fb    = (const float*)d_in[7];
    const float* pi    = (const float*)d_in[8];
    const float* sigma = (const float*)d_in[9];
    const float* omega = (const float*)d_in[10];

    // TMA descriptor for v: [L*N planes][FLEN rows][H1 cols] fp32.
    // Box = (64 cols, 98 rows, 1 plane); col offset selects the output half.
    CUtensorMap tmap;
    {
        static PFN_tme pfn = nullptr;
        if (!pfn) {
            cudaDriverEntryPointQueryResult qres;
            void* fp = nullptr;
            cudaGetDriverEntryPoint("cuTensorMapEncodeTiled", &fp,
                                    cudaEnableDefault, &qres);
            pfn = (PFN_tme)fp;
        }
        cuuint64_t dims[3]    = {H1, FLEN, (cuuint64_t)NL * NEL};
        cuuint64_t strides[2] = {H1 * 4, (cuuint64_t)FLEN * H1 * 4};
        cuuint32_t box[3]     = {64, ROWS_PER_STAGE, 1};
        cuuint32_t estr[3]    = {1, 1, 1};
        pfn(&tmap, CU_TENSOR_MAP_DATA_TYPE_FLOAT32, 3, (void*)v,
            dims, strides, box, estr,
            CU_TENSOR_MAP_INTERLEAVE_NONE, CU_TENSOR_MAP_SWIZZLE_NONE,
            CU_TENSOR_MAP_L2_PROMOTION_L2_128B, CU_TENSOR_MAP_FLOAT_OOB_FILL_NONE);
    }

    cudaFuncSetAttribute(fused_kernel,
                         cudaFuncAttributeMaxDynamicSharedMemorySize, DYN_BYTES);
    pre_kernel<<<1, 256>>>(ep, nuc);
    fused_kernel<<<GRID, THREADS, DYN_BYTES>>>(tmap, ep, nuc, b, w, c, fw, fb,
                                               pi, sigma, omega, (float*)d_out);
}